// round 2
// baseline (speedup 1.0000x reference)
#include <cuda_runtime.h>

// SpatialWeightsEsDot: att[b,h,w,1,49] = softmax_off( window-masked 3x3-boxsum of
//   M_{dy,dx}[y,x] = sum_c phi[b,c,y,x]*phi[b,c,y+dy,x+dx] ), phi = w_phi @ u (1x1 conv).
// Shapes fixed: u [2,64,128,128] f32, w_phi [64,64] f32, out [2,128,128,1,49] f32.

#define HH 128
#define WW 128
#define CC 64
#define TILE 8
#define MG 10            // M grid per block = TILE + 2 (3x3 boxsum halo)
#define PG 16            // phi tile per block = TILE + 2 + 6 (window halo)
#define SPITCH 68        // floats per phi-tile position (64 + 4 pad); conflict-free for LDS.128
#define NOFF 49
#define S_PHI_FLOATS (PG * PG * SPITCH)      // 17408
#define S_M_FLOATS   (NOFF * MG * MG)        // 4900
#define SMEM_BYTES   ((S_PHI_FLOATS + S_M_FLOATS) * 4)  // 89232 B -> 2 blocks/SM

// Scratch: phi in pixel-major layout [b][y][x][c] (c contiguous -> vectorized tile loads)
__device__ float g_phi[2 * HH * WW * CC];

// ---------------------------------------------------------------------------
// Kernel 1: phi[b,o,y,x] = sum_i w[o,i] * u[b,i,y,x]; stored pixel-major.
// 4 threads per pixel, 16 output channels each -> 131072 threads (~28 warps/SM).
// ---------------------------------------------------------------------------
__global__ void __launch_bounds__(256, 1)
phi_kernel(const float* __restrict__ u, const float* __restrict__ w) {
    __shared__ float s_w[CC * CC];
    int tid = threadIdx.x;
    for (int i = tid; i < CC * CC; i += 256) s_w[i] = w[i];
    __syncthreads();

    int t   = blockIdx.x * 256 + tid;          // 0..131071
    int og  = t & 3;                           // output-channel group (16 ch)
    int pix = t >> 2;                          // 0..32767
    int b   = pix >> 14;
    int p   = pix & 16383;

    const float* ub = u + b * CC * 16384 + p;
    float ur[CC];
#pragma unroll
    for (int i = 0; i < CC; i++) ur[i] = ub[i * 16384];

    float4* outp = (float4*)(g_phi + (size_t)pix * CC + og * 16);
    const float4* w4 = (const float4*)s_w;
    int obase = og * 16;

#pragma unroll
    for (int oo = 0; oo < 16; oo += 4) {
        float a0 = 0.f, a1 = 0.f, a2 = 0.f, a3 = 0.f;
        int o = obase + oo;
#pragma unroll
        for (int k = 0; k < CC / 4; k++) {
            float4 w0 = w4[(o + 0) * 16 + k];
            float4 w1 = w4[(o + 1) * 16 + k];
            float4 w2 = w4[(o + 2) * 16 + k];
            float4 w3 = w4[(o + 3) * 16 + k];
            float u0 = ur[4 * k + 0], u1 = ur[4 * k + 1];
            float u2 = ur[4 * k + 2], u3 = ur[4 * k + 3];
            a0 += w0.x * u0 + w0.y * u1 + w0.z * u2 + w0.w * u3;
            a1 += w1.x * u0 + w1.y * u1 + w1.z * u2 + w1.w * u3;
            a2 += w2.x * u0 + w2.y * u1 + w2.z * u2 + w2.w * u3;
            a3 += w3.x * u0 + w3.y * u1 + w3.z * u2 + w3.w * u3;
        }
        outp[oo >> 2] = make_float4(a0, a1, a2, a3);
    }
}

// ---------------------------------------------------------------------------
// Kernel 2: per 8x8 pixel tile — 16x16 phi halo in smem, 49 M maps on the
// 10x10 M grid (5 threads/position, center vec in regs), then boxsum + mask +
// softmax (8 threads/pixel, shfl reductions) + coalesced store via smem.
// ---------------------------------------------------------------------------
__global__ void __launch_bounds__(512, 2)
attn_kernel(float* __restrict__ out) {
    extern __shared__ float smem[];
    float* s_phi = smem;
    float* s_M   = smem + S_PHI_FLOATS;
    float* s_out = smem;                 // aliases phi region (dead after M phase)

    int tid = threadIdx.x;
    int b   = blockIdx.z;
    int h0  = blockIdx.y * TILE;
    int w0  = blockIdx.x * TILE;

    // ---- Load phi halo tile (16x16 positions x 64ch), zero outside image ----
    for (int idx = tid; idx < PG * PG * 16; idx += 512) {
        int pos = idx >> 4;
        int c4  = idx & 15;
        int py  = pos >> 4;
        int px  = pos & 15;
        int y = h0 - 4 + py;
        int x = w0 - 4 + px;
        float4 v = make_float4(0.f, 0.f, 0.f, 0.f);
        if ((unsigned)y < HH && (unsigned)x < WW)
            v = *(const float4*)(g_phi + ((((b << 7) + y) << 7) + x) * CC + (c4 << 2));
        *(float4*)(s_phi + pos * SPITCH + (c4 << 2)) = v;
    }
    __syncthreads();

    // ---- M maps: 5 threads per M-position, ~10 offsets each ----
    if (tid < 500) {
        int pos = tid / 5;
        int sub = tid - pos * 5;
        int my  = pos / MG;
        int mx  = pos - my * MG;
        const float4* cb = (const float4*)(s_phi + ((my + 3) * PG + (mx + 3)) * SPITCH);
        float4 c[16];
#pragma unroll
        for (int k = 0; k < 16; k++) c[k] = cb[k];

#pragma unroll 1
        for (int off = sub; off < NOFF; off += 5) {
            int oy = off / 7;
            int dy = oy - 3;
            int dx = off - oy * 7 - 3;
            const float4* sb = cb + (dy * PG + dx) * (SPITCH / 4);
            float a0 = 0.f, a1 = 0.f, a2 = 0.f, a3 = 0.f;
#pragma unroll
            for (int k = 0; k < 16; k += 4) {
                float4 v0 = sb[k + 0];
                float4 v1 = sb[k + 1];
                float4 v2 = sb[k + 2];
                float4 v3 = sb[k + 3];
                a0 += c[k + 0].x * v0.x + c[k + 0].y * v0.y + c[k + 0].z * v0.z + c[k + 0].w * v0.w;
                a1 += c[k + 1].x * v1.x + c[k + 1].y * v1.y + c[k + 1].z * v1.z + c[k + 1].w * v1.w;
                a2 += c[k + 2].x * v2.x + c[k + 2].y * v2.y + c[k + 2].z * v2.z + c[k + 2].w * v2.w;
                a3 += c[k + 3].x * v3.x + c[k + 3].y * v3.y + c[k + 3].z * v3.z + c[k + 3].w * v3.w;
            }
            s_M[off * (MG * MG) + pos] = (a0 + a1) + (a2 + a3);
        }
    }
    __syncthreads();

    // ---- Boxsum + mask + softmax: 8 threads per pixel, shfl-xor over 8 lanes ----
    {
        int pixloc = tid >> 3;           // 0..63
        int sub    = tid & 7;
        int py = pixloc >> 3;
        int px = pixloc & 7;
        int h = h0 + py;
        int w = w0 + px;

        float v[7];
        int n = 0;
        float mx_ = -1e30f;
#pragma unroll 1
        for (int off = sub; off < NOFF; off += 8) {
            int oy = off / 7;
            int dy = oy - 3;
            int dx = off - oy * 7 - 3;
            const float* m = s_M + off * (MG * MG) + py * MG + px;
            float s = m[0] + m[1] + m[2]
                    + m[MG] + m[MG + 1] + m[MG + 2]
                    + m[2 * MG] + m[2 * MG + 1] + m[2 * MG + 2];
            bool valid = ((unsigned)(h + dy) < HH) && ((unsigned)(w + dx) < WW);
            s = valid ? s : 0.0f;
            v[n++] = s;
            mx_ = fmaxf(mx_, s);
        }
#pragma unroll
        for (int d = 1; d < 8; d <<= 1)
            mx_ = fmaxf(mx_, __shfl_xor_sync(0xffffffffu, mx_, d));

        float sum = 0.f;
#pragma unroll
        for (int i = 0; i < 7; i++) {
            if (i < n) { v[i] = __expf(v[i] - mx_); sum += v[i]; }
        }
#pragma unroll
        for (int d = 1; d < 8; d <<= 1)
            sum += __shfl_xor_sync(0xffffffffu, sum, d);
        float inv = 1.0f / sum;

        int j = 0;
#pragma unroll 1
        for (int off = sub; off < NOFF; off += 8)
            s_out[pixloc * NOFF + off] = v[j++] * inv;
    }
    __syncthreads();

    // ---- Coalesced store: 8 rows of 392 contiguous floats each ----
    float* ob = out + ((size_t)((b * HH + h0) * WW + w0)) * NOFF;
    for (int i = tid; i < TILE * (TILE * NOFF); i += 512) {
        int row = i / (TILE * NOFF);
        int col = i - row * (TILE * NOFF);
        ob[row * (WW * NOFF) + col] = s_out[row * (TILE * NOFF) + col];
    }
}

extern "C" void kernel_launch(void* const* d_in, const int* in_sizes, int n_in,
                              void* d_out, int out_size) {
    const float* u = (const float*)d_in[0];    // [2,64,128,128]
    const float* w = (const float*)d_in[1];    // [64,64]
    float* out = (float*)d_out;                // [2,128,128,1,49]

    cudaFuncSetAttribute(attn_kernel, cudaFuncAttributeMaxDynamicSharedMemorySize, SMEM_BYTES);

    phi_kernel<<<(2 * HH * WW * 4) / 256, 256>>>(u, w);
    dim3 grid(WW / TILE, HH / TILE, 2);
    attn_kernel<<<grid, 512, SMEM_BYTES>>>(out);
}

// round 4
// speedup vs baseline: 2.0385x; 2.0385x over previous
#include <cuda_runtime.h>

// SpatialWeightsEsDot on GB300.
//   phi = w_phi @ u (1x1 conv), layout [b][c][y][x]
//   M_{dy,dx}[b][y][x] = sum_c phi[b,c,y,x]*phi[b,c,y+dy,x+dx]  (zero outside image)
//   score[p,d] = 1[p+d in image] * sum_{e in 3x3} M_d[p+e]
//   out = softmax over the 49 offsets -> [2,128,128,1,49]

#define HH 128
#define WW 128
#define CC 64

__device__ float g_phi[2 * CC * HH * WW];     // [b][c][y][x]
__device__ float g_M[49 * 2 * HH * WW];       // [off][b][y][x], off=(dy+3)*7+(dx+3)

// ---------------------------------------------------------------------------
// K1: phi. grid(128, 4og), block 256. Warp = 32 consecutive pixels (coalesced).
// Each thread: 16 output channels (og*16..), scalar accumulators, w from smem.
// ---------------------------------------------------------------------------
__global__ void __launch_bounds__(256)
phi_kernel(const float* __restrict__ u, const float* __restrict__ w) {
    __shared__ float s_wT[CC * CC];            // [k][o] transposed
    int tid = threadIdx.x;
    for (int i = tid; i < CC * CC; i += 256) {
        int k = i >> 6, o = i & 63;
        s_wT[i] = w[o * CC + k];
    }
    __syncthreads();

    int pix = blockIdx.x * 256 + tid;          // 0..32767
    int b   = pix >> 14;
    int p   = pix & 16383;
    int og  = blockIdx.y;                      // outputs og*16 .. og*16+15

    const float* ub = u + b * CC * 16384 + p;
    const float4* wt4 = (const float4*)s_wT;

    float acc[16];
#pragma unroll
    for (int i = 0; i < 16; i++) acc[i] = 0.f;

#pragma unroll 4
    for (int k = 0; k < CC; k++) {
        float uk = ub[k * 16384];
        float4 w0 = wt4[k * 16 + og * 4 + 0];
        float4 w1 = wt4[k * 16 + og * 4 + 1];
        float4 w2 = wt4[k * 16 + og * 4 + 2];
        float4 w3 = wt4[k * 16 + og * 4 + 3];
        acc[0]  += w0.x * uk; acc[1]  += w0.y * uk; acc[2]  += w0.z * uk; acc[3]  += w0.w * uk;
        acc[4]  += w1.x * uk; acc[5]  += w1.y * uk; acc[6]  += w1.z * uk; acc[7]  += w1.w * uk;
        acc[8]  += w2.x * uk; acc[9]  += w2.y * uk; acc[10] += w2.z * uk; acc[11] += w2.w * uk;
        acc[12] += w3.x * uk; acc[13] += w3.y * uk; acc[14] += w3.z * uk; acc[15] += w3.w * uk;
    }

    float* op = g_phi + (b * CC + og * 16) * 16384 + p;
#pragma unroll
    for (int o = 0; o < 16; o++) op[o * 16384] = acc[o];
}

// ---------------------------------------------------------------------------
// K2: M maps. grid 256 (one block per image row), block 224 = 7 warps (dy groups).
// Lane = 4 consecutive pixels. Per channel: 1 center LDG.128 + 3 shifted
// LDG.128 -> 12-float register window serves all 7 dx via shifted FMAs.
// Block groups all 7 dy for one row -> center row L1-shared on the same SM.
// ---------------------------------------------------------------------------
__global__ void __launch_bounds__(224)
m_kernel() {
    int lane = threadIdx.x & 31;
    int grp  = threadIdx.x >> 5;               // 0..6 -> dy = grp-3
    int row  = blockIdx.x;                     // 0..255
    int b = row >> 7, y = row & 127;
    int dy = grp - 3;
    int x  = lane << 2;
    int ys = y + dy;
    bool rowok = (unsigned)ys < (unsigned)HH;
    bool lok = (x > 0);
    bool rok = (x < WW - 4);

    const float* pcb = g_phi + b * CC * 16384 + y  * WW + x;   // +c*16384
    const float* psb = g_phi + b * CC * 16384 + ys * WW + x;

    float acc[28];
#pragma unroll
    for (int i = 0; i < 28; i++) acc[i] = 0.f;

#pragma unroll 2
    for (int c = 0; c < CC; c++) {
        const float* pc_ = pcb + c * 16384;
        const float* ps_ = psb + c * 16384;
        float4 ctr = *(const float4*)pc_;
        float4 w0 = make_float4(0.f, 0.f, 0.f, 0.f);
        float4 w1 = w0, w2 = w0;
        if (rowok) {
            w1 = *(const float4*)ps_;
            if (lok) w0 = *(const float4*)(ps_ - 4);
            if (rok) w2 = *(const float4*)(ps_ + 4);
        }
        float win[12] = {w0.x, w0.y, w0.z, w0.w,
                         w1.x, w1.y, w1.z, w1.w,
                         w2.x, w2.y, w2.z, w2.w};
        float ct[4] = {ctr.x, ctr.y, ctr.z, ctr.w};
#pragma unroll
        for (int d = 0; d < 7; d++)            // dx = d-3
#pragma unroll
            for (int j = 0; j < 4; j++)
                acc[d * 4 + j] += ct[j] * win[1 + d + j];   // phi_s[x+j+(d-3)]
    }

    float* mb = g_M + b * 16384 + y * WW + x;
#pragma unroll
    for (int d = 0; d < 7; d++)
        *(float4*)(mb + (size_t)(grp * 7 + d) * 32768) =
            make_float4(acc[d * 4], acc[d * 4 + 1], acc[d * 4 + 2], acc[d * 4 + 3]);
}

// ---------------------------------------------------------------------------
// K3: boxsum + mask + softmax. grid (2 xb, 128 y, 2 b), block 512.
// Thread (px 0..63, dyg 0..7; dyg==7 idle in compute). Lanes = consecutive x
// -> coalesced M reads. Cross-dy softmax via tiny smem reduction (pitch 9).
// ---------------------------------------------------------------------------
__global__ void __launch_bounds__(512)
attn_kernel(float* __restrict__ out) {
    __shared__ float s_red[64 * 9];
    int t   = threadIdx.x;
    int px  = t & 63;
    int dyg = t >> 6;                          // 0..7
    int b = blockIdx.z, y = blockIdx.y, x = blockIdx.x * 64 + px;

    float sc[7];
    float lmax = -1e30f;
    if (dyg < 7) {
        int dy = dyg - 3;
#pragma unroll
        for (int d3 = 0; d3 < 7; d3++) {
            int dx = d3 - 3;
            float s = 0.f;
            const float* mb = g_M + (size_t)(dyg * 7 + d3) * 32768 + b * 16384;
#pragma unroll
            for (int ey = -1; ey <= 1; ey++) {
                int yy = y + ey;
                if ((unsigned)yy < (unsigned)HH) {
#pragma unroll
                    for (int ex = -1; ex <= 1; ex++) {
                        int xx = x + ex;
                        if ((unsigned)xx < (unsigned)WW) s += mb[yy * WW + xx];
                    }
                }
            }
            bool valid = ((unsigned)(y + dy) < (unsigned)HH) &&
                         ((unsigned)(x + dx) < (unsigned)WW);
            sc[d3] = valid ? s : 0.f;
            lmax = fmaxf(lmax, sc[d3]);
        }
    }
    s_red[px * 9 + dyg] = lmax;                // dyg==7 writes -1e30 (ignored)
    __syncthreads();

    float gmax = s_red[px * 9 + 0];
#pragma unroll
    for (int j = 1; j < 7; j++) gmax = fmaxf(gmax, s_red[px * 9 + j]);

    float e[7];
    float lsum = 0.f;
    if (dyg < 7) {
#pragma unroll
        for (int d3 = 0; d3 < 7; d3++) { e[d3] = __expf(sc[d3] - gmax); lsum += e[d3]; }
    }
    __syncthreads();                           // protect s_red before overwrite
    s_red[px * 9 + dyg] = lsum;                // dyg==7 writes 0 (lsum init, not read)
    __syncthreads();

    float gsum = 0.f;
#pragma unroll
    for (int j = 0; j < 7; j++) gsum += s_red[px * 9 + j];

    if (dyg < 7) {
        float inv = 1.0f / gsum;
        float* op = out + (size_t)(b * 16384 + y * WW + x) * 49 + dyg * 7;
#pragma unroll
        for (int d3 = 0; d3 < 7; d3++) op[d3] = e[d3] * inv;
    }
}

extern "C" void kernel_launch(void* const* d_in, const int* in_sizes, int n_in,
                              void* d_out, int out_size) {
    const float* u = (const float*)d_in[0];    // [2,64,128,128]
    const float* w = (const float*)d_in[1];    // [64,64]
    float* out = (float*)d_out;                // [2,128,128,1,49]

    phi_kernel<<<dim3(128, 4), 256>>>(u, w);
    m_kernel<<<256, 224>>>();
    attn_kernel<<<dim3(2, 128, 2), 512>>>(out);
}